// round 14
// baseline (speedup 1.0000x reference)
#include <cuda_runtime.h>
#include <cuda_fp16.h>
#include <math.h>

#define NN  100000
#define EE  1600000
#define C   64
#define OC  16
#define CAP 64          // max non-self neighbors (Poisson(16): P(>64)~e^-40)

// ---------------- device scratch (no allocations allowed) ----------------
__device__ int   g_fill[NN];
__device__ __align__(256) int g_col[(size_t)NN * CAP];   // sentinel-padded CSR
__device__ int   g_is64;
// fp16 feature buffers + dummy zero row at index NN
__device__ __align__(256) __half g_bufA[(size_t)(NN + 1) * C];
__device__ __align__(256) __half g_bufB[(size_t)(NN + 1) * C];

union HU { uint4 u; __half2 h[4]; };

__device__ __forceinline__ int edge_src(const void* ei, int e) {
    if (g_is64) return (int)((const long long*)ei)[e];
    return ((const int*)ei)[e];
}
__device__ __forceinline__ int edge_dst(const void* ei, int e) {
    if (g_is64) return (int)((const long long*)ei)[EE + e];
    return ((const int*)ei)[EE + e];
}

// ---------------- init: counters, sentinel CSR, dummy rows, dtype ----------
__global__ void k_init(const unsigned* __restrict__ ei) {
    int i = blockIdx.x * blockDim.x + threadIdx.x;
    if (i < NN * (CAP / 4))
        reinterpret_cast<int4*>(g_col)[i] = make_int4(NN, NN, NN, NN);
    if (i < NN) g_fill[i] = 0;
    if (i < 8) {
        reinterpret_cast<uint4*>(g_bufA + (size_t)NN * C)[i] = make_uint4(0,0,0,0);
        reinterpret_cast<uint4*>(g_bufB + (size_t)NN * C)[i] = make_uint4(0,0,0,0);
    }
    if (i == 0) {
        int is64 = 1;
        for (int t = 0; t < 64; t++)
            if (ei[2 * t + 1] != 0u) { is64 = 0; break; }
        g_is64 = is64;
    }
}

// ---------------- single-pass bucket fill ----------------
__global__ void k_fill(const void* __restrict__ ei) {
    int e = blockIdx.x * blockDim.x + threadIdx.x;
    if (e < EE) {
        int d = edge_dst(ei, e);
        int s = edge_src(ei, e);
        if ((unsigned)d < NN && (unsigned)s < NN) {
            int p = atomicAdd(&g_fill[d], 1);
            if (p < CAP) g_col[(size_t)d * CAP + p] = s;
        }
    }
}

// ---------------- cp.async helpers ----------------
__device__ __forceinline__ void cpa16(unsigned dst, const void* src) {
    asm volatile("cp.async.cg.shared.global [%0], [%1], 16;"
                 :: "r"(dst), "l"(src) : "memory");
}
#define CP_COMMIT() asm volatile("cp.async.commit_group;" ::: "memory")

// ---------------- cp.async staged aggregation: 4 nodes per warp ------------
// Chunk = 4 neighbors/node. One cpa16 warp-instruction stages 4 rows of one
// node (lane: oct=row-in-chunk, sub=16B slice). Double-buffered 2x2KB/warp.
// Sentinel rows (index NN) are zeros -> branch-free inner loop.
// Stage layout (bytes, per 2KB buffer): rr*512 + n*128 + sub*16.
__device__ __forceinline__ void agg4_cp(const __half* __restrict__ G,
                                        char* stw, int lane, int node0,
                                        float2 (&aout)[4], int (&degv)[4]) {
    int oct = lane >> 3, sub = lane & 7;
    unsigned staddr = (unsigned)__cvta_generic_to_shared(stw);
    const int* cols[4];
    int cnt[4];
    #pragma unroll
    for (int rr = 0; rr < 4; rr++) {
        int node = node0 + rr;
        int d = g_fill[node];
        degv[rr] = d;
        cnt[rr] = d < CAP ? d : CAP;
        cols[rr] = g_col + (size_t)node * CAP;
        aout[rr] = __half22float2(
            __ldcg(reinterpret_cast<const __half2*>(G + (size_t)node * C) + lane));
    }
    int mxc = max(max(cnt[0], cnt[1]), max(cnt[2], cnt[3]));
    int nch = (mxc + 3) >> 2;
    if (nch == 0) return;

    // prologue: stage chunk 0 into buf 0
    #pragma unroll
    for (int rr = 0; rr < 4; rr++) {
        int4 j4 = *reinterpret_cast<const int4*>(cols[rr]);
        int j = (oct == 0) ? j4.x : (oct == 1) ? j4.y : (oct == 2) ? j4.z : j4.w;
        cpa16(staddr + rr * 512 + oct * 128 + sub * 16, G + (size_t)j * C + sub * 8);
    }
    CP_COMMIT();

    for (int ch = 0; ch < nch; ch++) {
        if (ch + 1 < nch) {
            unsigned nb = ((unsigned)(ch + 1) & 1u) * 2048u;
            #pragma unroll
            for (int rr = 0; rr < 4; rr++) {
                int4 j4 = *reinterpret_cast<const int4*>(cols[rr] + 4 * (ch + 1));
                int j = (oct == 0) ? j4.x : (oct == 1) ? j4.y : (oct == 2) ? j4.z : j4.w;
                cpa16(staddr + nb + rr * 512 + oct * 128 + sub * 16,
                      G + (size_t)j * C + sub * 8);
            }
        }
        CP_COMMIT();                                    // possibly empty group
        asm volatile("cp.async.wait_group 1;" ::: "memory");
        __syncwarp();
        const __half2* sb = reinterpret_cast<const __half2*>(stw + (ch & 1) * 2048);
        #pragma unroll
        for (int rr = 0; rr < 4; rr++) {
            #pragma unroll
            for (int n = 0; n < 4; n++) {
                // row (rr,n) starts at byte rr*512 + n*128 -> half2 idx rr*128+n*32
                float2 f = __half22float2(sb[rr * 128 + n * 32 + lane]);
                aout[rr].x += f.x; aout[rr].y += f.y;
            }
        }
        __syncwarp();                                   // WAR before re-staging
    }
    asm volatile("cp.async.wait_group 0;" ::: "memory");
}

// ---------------- layer-1 GEMM: G1 = dinv * (x @ W1) -> g_bufA (fp16) -------
__global__ void k_gemm_scale(const float* __restrict__ in,
                             const float* __restrict__ W) {
    __shared__ __align__(16) float xs[32][68];
    __shared__ __align__(16) float Ws[C][C];
    int tid  = threadIdx.x;
    int row0 = blockIdx.x * 32;

    for (int i4 = tid; i4 < 32 * 16; i4 += 256) {
        float4 v = reinterpret_cast<const float4*>(in + (size_t)row0 * C)[i4];
        *reinterpret_cast<float4*>(&xs[i4 >> 4][(i4 & 15) * 4]) = v;
    }
    for (int i4 = tid; i4 < 16 * C; i4 += 256)
        reinterpret_cast<float4*>(&Ws[0][0])[i4] =
            reinterpret_cast<const float4*>(W)[i4];
    __syncthreads();

    int n  = tid >> 3;
    int c0 = (tid & 7) * 8;
    float acc[8];
    #pragma unroll
    for (int j = 0; j < 8; j++) acc[j] = 0.f;

    #pragma unroll
    for (int k = 0; k < C; k++) {
        float xv = xs[n][k];
        float4 w0 = *reinterpret_cast<const float4*>(&Ws[k][c0]);
        float4 w1 = *reinterpret_cast<const float4*>(&Ws[k][c0 + 4]);
        acc[0] += xv * w0.x; acc[1] += xv * w0.y;
        acc[2] += xv * w0.z; acc[3] += xv * w0.w;
        acc[4] += xv * w1.x; acc[5] += xv * w1.y;
        acc[6] += xv * w1.z; acc[7] += xv * w1.w;
    }

    float dv = rsqrtf((float)(g_fill[row0 + n] + 1));
    HU P;
    P.h[0] = __floats2half2_rn(acc[0]*dv, acc[1]*dv);
    P.h[1] = __floats2half2_rn(acc[2]*dv, acc[3]*dv);
    P.h[2] = __floats2half2_rn(acc[4]*dv, acc[5]*dv);
    P.h[3] = __floats2half2_rn(acc[6]*dv, acc[7]*dv);
    *reinterpret_cast<uint4*>(g_bufA + (size_t)(row0 + n) * C + c0) = P.u;
}

// ---------------- fused agg(L1) + relu + GEMM(W2, fp16 smem) -> g_bufB ------
// static: Wsh 8KB. dynamic: 32KB stage (8 warps x 4KB), REUSED as xs tile
// after aggregation (block-synced). Total smem 40KB < 48KB limit.
__global__ void k_agg_gemm(const float* __restrict__ bias,
                           const float* __restrict__ W2) {
    extern __shared__ char stage[];
    __shared__ __align__(16) __half2 Wsh[C * 32];   // [k][32 half2]
    int tid  = threadIdx.x;
    int warp = tid >> 5;
    int lane = tid & 31;
    int row0 = blockIdx.x * 32;

    for (int i = tid; i < C * 32; i += 256) {
        float2 w = reinterpret_cast<const float2*>(W2)[i];
        Wsh[i] = __floats2half2_rn(w.x, w.y);
    }

    float2 aout[4]; int degv[4];
    agg4_cp(g_bufA, stage + warp * 4096, lane, row0 + warp * 4, aout, degv);

    __syncthreads();                 // all warps done with stage -> reuse as xs
    float* xsf = reinterpret_cast<float*>(stage);    // [32][68]

    const float2 bv = reinterpret_cast<const float2*>(bias)[lane];
    #pragma unroll
    for (int rr = 0; rr < 4; rr++) {
        float dv = rsqrtf((float)(degv[rr] + 1));
        float* xr = xsf + (warp * 4 + rr) * 68;
        xr[2 * lane]     = fmaxf(fmaf(dv, aout[rr].x, bv.x), 0.f);
        xr[2 * lane + 1] = fmaxf(fmaf(dv, aout[rr].y, bv.y), 0.f);
    }
    __syncthreads();

    int n   = tid >> 3;
    int c0h = (tid & 7) * 4;    // half2 column base (8 fp32 cols)
    float acc[8];
    #pragma unroll
    for (int j = 0; j < 8; j++) acc[j] = 0.f;

    const float* xr = xsf + n * 68;
    #pragma unroll
    for (int k = 0; k < C; k++) {
        float xv = xr[k];
        float2 f0 = __half22float2(Wsh[k * 32 + c0h]);
        float2 f1 = __half22float2(Wsh[k * 32 + c0h + 1]);
        float2 f2 = __half22float2(Wsh[k * 32 + c0h + 2]);
        float2 f3 = __half22float2(Wsh[k * 32 + c0h + 3]);
        acc[0] += xv * f0.x; acc[1] += xv * f0.y;
        acc[2] += xv * f1.x; acc[3] += xv * f1.y;
        acc[4] += xv * f2.x; acc[5] += xv * f2.y;
        acc[6] += xv * f3.x; acc[7] += xv * f3.y;
    }

    float dv = rsqrtf((float)(g_fill[row0 + n] + 1));
    HU P;
    P.h[0] = __floats2half2_rn(acc[0]*dv, acc[1]*dv);
    P.h[1] = __floats2half2_rn(acc[2]*dv, acc[3]*dv);
    P.h[2] = __floats2half2_rn(acc[4]*dv, acc[5]*dv);
    P.h[3] = __floats2half2_rn(acc[6]*dv, acc[7]*dv);
    *reinterpret_cast<uint4*>(g_bufB + (size_t)(row0 + n) * C + (tid & 7) * 8) = P.u;
}

// ---------------- fused agg(L2) + relu + FC + log_softmax -> out ------------
__global__ void k_agg_final(const float* __restrict__ b2,
                            const float* __restrict__ Wfc,
                            const float* __restrict__ bfc,
                            float* __restrict__ out) {
    extern __shared__ char stage[];
    __shared__ __align__(16) float Wt[OC][C];   // Wt[c][k] = Wfc[k][c]
    __shared__ float bs[OC];
    int tid = threadIdx.x;
    for (int i = tid; i < C * OC; i += 256) {
        int k = i >> 4, c = i & 15;
        Wt[c][k] = Wfc[i];
    }
    if (tid < OC) bs[tid] = bfc[tid];
    __syncthreads();

    int warp = tid >> 5;
    int lane = tid & 31;
    int node0 = blockIdx.x * 32 + warp * 4;

    float2 aout[4]; int degv[4];
    agg4_cp(g_bufB, stage + warp * 4096, lane, node0, aout, degv);

    const float2 bv = reinterpret_cast<const float2*>(b2)[lane];
    #pragma unroll
    for (int rr = 0; rr < 4; rr++) {
        float dv = rsqrtf((float)(degv[rr] + 1));
        float h0 = fmaxf(fmaf(dv, aout[rr].x, bv.x), 0.f);
        float h1 = fmaxf(fmaf(dv, aout[rr].y, bv.y), 0.f);

        float logit = 0.f;
        #pragma unroll
        for (int c = 0; c < OC; c++) {
            float2 w = *reinterpret_cast<const float2*>(&Wt[c][2 * lane]);
            float p = h0 * w.x + h1 * w.y;
            #pragma unroll
            for (int off = 16; off; off >>= 1)
                p += __shfl_xor_sync(0xffffffffu, p, off);
            if (lane == c) logit = p + bs[c];
        }
        float v = (lane < OC) ? logit : -3.4e38f;
        float mx = v;
        #pragma unroll
        for (int off = 16; off; off >>= 1)
            mx = fmaxf(mx, __shfl_xor_sync(0xffffffffu, mx, off));
        float ex = (lane < OC) ? expf(logit - mx) : 0.f;
        float sm = ex;
        #pragma unroll
        for (int off = 16; off; off >>= 1)
            sm += __shfl_xor_sync(0xffffffffu, sm, off);
        if (lane < OC)
            out[(size_t)(node0 + rr) * OC + lane] = logit - mx - logf(sm);
    }
}

// ---------------- launch (5 launches; ncu captures launch #4) ---------------
extern "C" void kernel_launch(void* const* d_in, const int* in_sizes, int n_in,
                              void* d_out, int out_size) {
    const float* x   = (const float*)d_in[0];
    const void*  ei  = d_in[1];
    const float* W1  = (const float*)d_in[2];
    const float* b1  = (const float*)d_in[3];
    const float* W2  = (const float*)d_in[4];
    const float* b2  = (const float*)d_in[5];
    const float* Wfc = (const float*)d_in[6];
    const float* bfc = (const float*)d_in[7];
    float* out = (float*)d_out;

    const int TB = 256;
    const int gI = (NN * (CAP / 4) + TB - 1) / TB;
    const int gE = (EE + TB - 1) / TB;
    const int gG = NN / 32;                           // 3125 (32 nodes/block)
    const int STG = 8 * 4096;                          // 32KB stage

    k_init<<<gI, TB>>>((const unsigned*)ei);            // 1
    k_fill<<<gE, TB>>>(ei);                              // 2
    k_gemm_scale<<<gG, TB>>>(x, W1);                     // 3
    k_agg_gemm<<<gG, TB, STG>>>(b1, W2);                 // 4  (ncu target)
    k_agg_final<<<gG, TB, STG>>>(b2, Wfc, bfc, out);     // 5
}

// round 16
// speedup vs baseline: 1.7674x; 1.7674x over previous
#include <cuda_runtime.h>
#include <cuda_fp16.h>
#include <math.h>

#define NN  100000
#define EE  1600000
#define C   64
#define OC  16
#define CAP 64          // max non-self neighbors per node (Poisson(16): P(>64)~e^-40)

// ---------------- device scratch (no allocations allowed) ----------------
__device__ int   g_fill[NN];                      // neighbor count (excl. self)
__device__ __align__(256) int g_col[(size_t)NN * CAP];   // padded bucket CSR
__device__ int   g_is64;                          // edge dtype flag
// fp16 feature buffers
__device__ __align__(256) __half g_bufA[(size_t)NN * C];  // G1 = dinv*(x@W1)
__device__ __align__(256) __half g_bufB[(size_t)NN * C];  // G2 = dinv*(H1@W2)

union HU { uint4 u; __half2 h[4]; };

__device__ __forceinline__ int edge_src(const void* ei, int e) {
    if (g_is64) return (int)((const long long*)ei)[e];
    return ((const int*)ei)[e];
}
__device__ __forceinline__ int edge_dst(const void* ei, int e) {
    if (g_is64) return (int)((const long long*)ei)[EE + e];
    return ((const int*)ei)[EE + e];
}

// ---------------- init + dtype detection ----------------
__global__ void k_init(const unsigned* __restrict__ ei) {
    int i = blockIdx.x * blockDim.x + threadIdx.x;
    if (i < NN) g_fill[i] = 0;
    if (i == 0) {
        int is64 = 1;
        for (int t = 0; t < 64; t++)
            if (ei[2 * t + 1] != 0u) { is64 = 0; break; }
        g_is64 = is64;
    }
}

// ---------------- single-pass bucket fill ----------------
__global__ void k_fill(const void* __restrict__ ei) {
    int e = blockIdx.x * blockDim.x + threadIdx.x;
    if (e < EE) {
        int d = edge_dst(ei, e);
        int s = edge_src(ei, e);
        if ((unsigned)d < NN && (unsigned)s < NN) {
            int p = atomicAdd(&g_fill[d], 1);
            if (p < CAP) g_col[(size_t)d * CAP + p] = s;
        }
    }
}

// ---------------- R9 gather core (proven fastest) ----------------
__device__ __forceinline__ void gather4(const __half2* __restrict__ Gh, int lane,
                                        const int* __restrict__ cp, int e, float2& a) {
    int4 j = *reinterpret_cast<const int4*>(cp + e);
    float2 u0 = __half22float2(__ldcg(Gh + (size_t)j.x * 32 + lane));
    float2 u1 = __half22float2(__ldcg(Gh + (size_t)j.y * 32 + lane));
    float2 u2 = __half22float2(__ldcg(Gh + (size_t)j.z * 32 + lane));
    float2 u3 = __half22float2(__ldcg(Gh + (size_t)j.w * 32 + lane));
    a.x += (u0.x + u1.x) + (u2.x + u3.x);
    a.y += (u0.y + u1.y) + (u2.y + u3.y);
}

__device__ __forceinline__ void agg4(const __half2* __restrict__ Gh, int lane,
                                     int node0, float2 (&a)[4], int (&degv)[4]) {
    int cnt[4];
    const int* cp[4];
    #pragma unroll
    for (int rr = 0; rr < 4; rr++) {
        int node = node0 + rr;
        int d = g_fill[node];
        degv[rr] = d;
        cnt[rr] = d < CAP ? d : CAP;
        cp[rr] = g_col + (size_t)node * CAP;
        a[rr] = __half22float2(__ldcg(Gh + (size_t)node * 32 + lane));
    }
    int mxc = max(max(cnt[0], cnt[1]), max(cnt[2], cnt[3]));
    for (int e = 0; e + 4 <= mxc; e += 4) {
        #pragma unroll
        for (int rr = 0; rr < 4; rr++)
            if (e + 4 <= cnt[rr]) gather4(Gh, lane, cp[rr], e, a[rr]);
    }
    #pragma unroll
    for (int rr = 0; rr < 4; rr++)
        for (int e = cnt[rr] & ~3; e < cnt[rr]; e++) {
            float2 u = __half22float2(__ldcg(Gh + (size_t)cp[rr][e] * 32 + lane));
            a[rr].x += u.x; a[rr].y += u.y;
        }
}

// ---------------- layer-1 GEMM: G1 = dinv * (x @ W1) -> g_bufA (fp16) -------
__global__ void k_gemm_scale(const float* __restrict__ in,
                             const float* __restrict__ W) {
    __shared__ __align__(16) float xs[32][68];
    __shared__ __align__(16) float Ws[C][C];
    int tid  = threadIdx.x;
    int row0 = blockIdx.x * 32;

    for (int i4 = tid; i4 < 32 * 16; i4 += 256) {
        float4 v = reinterpret_cast<const float4*>(in + (size_t)row0 * C)[i4];
        *reinterpret_cast<float4*>(&xs[i4 >> 4][(i4 & 15) * 4]) = v;
    }
    for (int i4 = tid; i4 < 16 * C; i4 += 256)
        reinterpret_cast<float4*>(&Ws[0][0])[i4] =
            reinterpret_cast<const float4*>(W)[i4];
    __syncthreads();

    int n  = tid >> 3;
    int c0 = (tid & 7) * 8;
    float acc[8];
    #pragma unroll
    for (int j = 0; j < 8; j++) acc[j] = 0.f;

    #pragma unroll
    for (int k = 0; k < C; k++) {
        float xv = xs[n][k];
        float4 w0 = *reinterpret_cast<const float4*>(&Ws[k][c0]);
        float4 w1 = *reinterpret_cast<const float4*>(&Ws[k][c0 + 4]);
        acc[0] += xv * w0.x; acc[1] += xv * w0.y;
        acc[2] += xv * w0.z; acc[3] += xv * w0.w;
        acc[4] += xv * w1.x; acc[5] += xv * w1.y;
        acc[6] += xv * w1.z; acc[7] += xv * w1.w;
    }

    float dv = rsqrtf((float)(g_fill[row0 + n] + 1));
    HU P;
    P.h[0] = __floats2half2_rn(acc[0]*dv, acc[1]*dv);
    P.h[1] = __floats2half2_rn(acc[2]*dv, acc[3]*dv);
    P.h[2] = __floats2half2_rn(acc[4]*dv, acc[5]*dv);
    P.h[3] = __floats2half2_rn(acc[6]*dv, acc[7]*dv);
    *reinterpret_cast<uint4*>(g_bufA + (size_t)(row0 + n) * C + c0) = P.u;
}

// ---------------- fused agg(L1) + relu + GEMM(W2) + scale -> g_bufB ---------
__global__ void __launch_bounds__(256, 6)
k_agg_gemm(const float* __restrict__ bias, const float* __restrict__ W2) {
    __shared__ __align__(16) float xs[32][68];
    __shared__ __align__(16) float Ws[C][C];
    int tid  = threadIdx.x;
    int warp = tid >> 5;
    int lane = tid & 31;
    int row0 = blockIdx.x * 32;

    for (int i4 = tid; i4 < 16 * C; i4 += 256)
        reinterpret_cast<float4*>(&Ws[0][0])[i4] =
            reinterpret_cast<const float4*>(W2)[i4];

    const float2 bv = reinterpret_cast<const float2*>(bias)[lane];
    const __half2* __restrict__ Gh = reinterpret_cast<const __half2*>(g_bufA);

    float2 a[4]; int degv[4];
    agg4(Gh, lane, row0 + warp * 4, a, degv);

    #pragma unroll
    for (int rr = 0; rr < 4; rr++) {
        float dv = rsqrtf((float)(degv[rr] + 1));
        xs[warp * 4 + rr][2 * lane]     = fmaxf(fmaf(dv, a[rr].x, bv.x), 0.f);
        xs[warp * 4 + rr][2 * lane + 1] = fmaxf(fmaf(dv, a[rr].y, bv.y), 0.f);
    }
    __syncthreads();

    int n  = tid >> 3;
    int c0 = (tid & 7) * 8;
    float acc[8];
    #pragma unroll
    for (int j = 0; j < 8; j++) acc[j] = 0.f;

    #pragma unroll
    for (int k = 0; k < C; k++) {
        float xv = xs[n][k];
        float4 w0 = *reinterpret_cast<const float4*>(&Ws[k][c0]);
        float4 w1 = *reinterpret_cast<const float4*>(&Ws[k][c0 + 4]);
        acc[0] += xv * w0.x; acc[1] += xv * w0.y;
        acc[2] += xv * w0.z; acc[3] += xv * w0.w;
        acc[4] += xv * w1.x; acc[5] += xv * w1.y;
        acc[6] += xv * w1.z; acc[7] += xv * w1.w;
    }

    float dv = rsqrtf((float)(g_fill[row0 + n] + 1));
    HU P;
    P.h[0] = __floats2half2_rn(acc[0]*dv, acc[1]*dv);
    P.h[1] = __floats2half2_rn(acc[2]*dv, acc[3]*dv);
    P.h[2] = __floats2half2_rn(acc[4]*dv, acc[5]*dv);
    P.h[3] = __floats2half2_rn(acc[6]*dv, acc[7]*dv);
    *reinterpret_cast<uint4*>(g_bufB + (size_t)(row0 + n) * C + c0) = P.u;
}

// ---------------- fused agg(L2) + relu + FC + log_softmax -> out ------------
// NEW epilogue: transposed smem FC (zero shuffles) + 16-lane-group softmax.
__global__ void __launch_bounds__(256, 6)
k_agg_final(const float* __restrict__ b2, const float* __restrict__ Wfc,
            const float* __restrict__ bfc, float* __restrict__ out) {
    __shared__ __align__(16) float Wt[OC][C];   // Wt[c][k] = Wfc[k][c]
    __shared__ float bs[OC];
    __shared__ float xsT[C][33];                // [k][node], conflict-free
    __shared__ float lg[32][OC + 1];            // logits [node][class]
    int tid = threadIdx.x;
    for (int i = tid; i < C * OC; i += 256) {
        int k = i >> 4, c = i & 15;
        Wt[c][k] = Wfc[i];
    }
    if (tid < OC) bs[tid] = bfc[tid];
    __syncthreads();

    int warp = tid >> 5;
    int lane = tid & 31;
    int node0 = blockIdx.x * 32 + warp * 4;

    const float2 bv = reinterpret_cast<const float2*>(b2)[lane];
    const __half2* __restrict__ Gh = reinterpret_cast<const __half2*>(g_bufB);

    float2 a[4]; int degv[4];
    agg4(Gh, lane, node0, a, degv);

    #pragma unroll
    for (int rr = 0; rr < 4; rr++) {
        float dv = rsqrtf((float)(degv[rr] + 1));
        int n = warp * 4 + rr;
        xsT[2 * lane][n]     = fmaxf(fmaf(dv, a[rr].x, bv.x), 0.f);
        xsT[2 * lane + 1][n] = fmaxf(fmaf(dv, a[rr].y, bv.y), 0.f);
    }
    __syncthreads();

    // FC: warp w owns classes w and w+8; lane owns node. No shuffles.
    {
        int n  = lane;
        int ca = warp;          // class a
        int cb = warp + 8;      // class b
        float la = bs[ca], lb = bs[cb];
        #pragma unroll
        for (int k = 0; k < C; k++) {
            float xv = xsT[k][n];           // conflict-free across lanes
            la = fmaf(xv, Wt[ca][k], la);   // broadcast within warp
            lb = fmaf(xv, Wt[cb][k], lb);
        }
        lg[n][ca] = la;
        lg[n][cb] = lb;
    }
    __syncthreads();

    // softmax: 16 threads per node (lane group), 2 passes over 32 nodes
    int nd  = tid >> 4;         // 0..15
    int cls = tid & 15;
    #pragma unroll
    for (int half = 0; half < 2; half++) {
        int n = nd + half * 16;
        float lv = lg[n][cls];
        float mx = lv;
        #pragma unroll
        for (int off = 8; off; off >>= 1)
            mx = fmaxf(mx, __shfl_xor_sync(0xffffffffu, mx, off));
        float ex = expf(lv - mx);
        float sm = ex;
        #pragma unroll
        for (int off = 8; off; off >>= 1)
            sm += __shfl_xor_sync(0xffffffffu, sm, off);
        out[(size_t)(blockIdx.x * 32 + n) * OC + cls] = lv - mx - logf(sm);
    }
}

// ---------------- launch (5 launches; ncu captures launch #4) ---------------
extern "C" void kernel_launch(void* const* d_in, const int* in_sizes, int n_in,
                              void* d_out, int out_size) {
    const float* x   = (const float*)d_in[0];
    const void*  ei  = d_in[1];
    const float* W1  = (const float*)d_in[2];
    const float* b1  = (const float*)d_in[3];
    const float* W2  = (const float*)d_in[4];
    const float* b2  = (const float*)d_in[5];
    const float* Wfc = (const float*)d_in[6];
    const float* bfc = (const float*)d_in[7];
    float* out = (float*)d_out;

    const int TB = 256;
    const int gN = (NN + TB - 1) / TB;
    const int gE = (EE + TB - 1) / TB;
    const int gG = NN / 32;                    // 3125 (32 nodes/block)

    k_init<<<gN, TB>>>((const unsigned*)ei);            // 1
    k_fill<<<gE, TB>>>(ei);                              // 2
    k_gemm_scale<<<gG, TB>>>(x, W1);                     // 3
    k_agg_gemm<<<gG, TB>>>(b1, W2);                      // 4  (ncu target)
    k_agg_final<<<gG, TB>>>(b2, Wfc, bfc, out);          // 5
}